// round 11
// baseline (speedup 1.0000x reference)
#include <cuda_runtime.h>
#include <cuda_bf16.h>

// Problem constants (fixed by setup_inputs)
#define BB    8
#define CC    64
#define NPTS  65536
#define RR    32
#define R3    (RR*RR*RR)           // 32768
#define NVOX  (BB*R3)              // 262144
#define NPTS_TOT (BB*NPTS)         // 524288
#define VOX_ELEMS  (BB*CC*R3)      // 16777216
#define NORM_ELEMS (BB*3*NPTS)     // 1572864
#define CH    32                    // channels per pass (2 passes)

// Scratch (device globals, zero-init at load).
// g_cnt is re-zeroed by scan_chunk each launch; everything else written fully.
__device__ float g_featT[(size_t)NPTS_TOT * CH];  // 64 MB: per-point 128B rows (sorted), reused across the 2 passes
__device__ int   g_cnt[NVOX];                     // per-voxel counts (reset each launch)
__device__ int   g_voxlocal[NVOX + 1];            // chunk-local exclusive offsets; [NVOX] stays 0
__device__ int   g_bsum[512];                     // chunk totals
__device__ int   g_boff[513];                     // chunk exclusive prefix; [512] = total
__device__ int   g_idx[NPTS_TOT];
__device__ unsigned short g_rank[NPTS_TOT];

// ---------------------------------------------------------------------------
// Kernel 1: per-point quantization, 4 points/thread (float4 I/O, 4 atomics in
// flight to hide ATOMG latency). norm_coords out, voxel idx, count+rank.
// ---------------------------------------------------------------------------
__global__ void point_kernel(const float* __restrict__ coords,
                             float* __restrict__ norm_out) {
    int tid = blockIdx.x * blockDim.x + threadIdx.x;  // NPTS_TOT/4 threads
    int pt0 = tid * 4;
    int b = pt0 >> 16;
    int n = pt0 & (NPTS - 1);

    const float* cb = coords + (size_t)b * 3 * NPTS + n;
    float4 x4 = *reinterpret_cast<const float4*>(cb);
    float4 y4 = *reinterpret_cast<const float4*>(cb + NPTS);
    float4 z4 = *reinterpret_cast<const float4*>(cb + 2 * NPTS);

    float nx[4] = {x4.x, x4.y, x4.z, x4.w};
    float ny[4] = {y4.x, y4.y, y4.z, y4.w};
    float nz[4] = {z4.x, z4.y, z4.z, z4.w};
    int gidx[4];
    #pragma unroll
    for (int i = 0; i < 4; i++) {
        nx[i] = fminf(fmaxf(nx[i] * (float)RR, 0.0f), (float)(RR - 1));
        ny[i] = fminf(fmaxf(ny[i] * (float)RR, 0.0f), (float)(RR - 1));
        nz[i] = fminf(fmaxf(nz[i] * (float)RR, 0.0f), (float)(RR - 1));
        int vx = __float2int_rn(nx[i]);   // round-half-even == jnp.round
        int vy = __float2int_rn(ny[i]);
        int vz = __float2int_rn(nz[i]);
        gidx[i] = b * R3 + (vx * RR + vy) * RR + vz;
    }

    if (norm_out) {
        float* nb = norm_out + (size_t)b * 3 * NPTS + n;
        *reinterpret_cast<float4*>(nb)            = make_float4(nx[0], nx[1], nx[2], nx[3]);
        *reinterpret_cast<float4*>(nb + NPTS)     = make_float4(ny[0], ny[1], ny[2], ny[3]);
        *reinterpret_cast<float4*>(nb + 2 * NPTS) = make_float4(nz[0], nz[1], nz[2], nz[3]);
    }

    *reinterpret_cast<int4*>(&g_idx[pt0]) = make_int4(gidx[0], gidx[1], gidx[2], gidx[3]);

    unsigned short r[4];
    #pragma unroll
    for (int i = 0; i < 4; i++)
        r[i] = (unsigned short)atomicAdd(&g_cnt[gidx[i]], 1);
    *reinterpret_cast<ushort4*>(&g_rank[pt0]) = make_ushort4(r[0], r[1], r[2], r[3]);
}

// ---------------------------------------------------------------------------
// Kernel 2a: per-chunk (512 counts) local exclusive scan via warp shuffles.
// Writes g_voxlocal, chunk total to g_bsum, and resets g_cnt.
// ---------------------------------------------------------------------------
__global__ void scan_chunk_kernel() {
    __shared__ int wsum[8];
    __shared__ int woff[8];
    int t = threadIdx.x;                 // 256 threads
    int lane = t & 31, w = t >> 5;

    int2 c = reinterpret_cast<const int2*>(g_cnt)[blockIdx.x * 256 + t];
    int s = c.x + c.y;

    int v = s;
    #pragma unroll
    for (int d = 1; d < 32; d <<= 1) {
        int u = __shfl_up_sync(0xffffffffu, v, d);
        if (lane >= d) v += u;
    }
    if (lane == 31) wsum[w] = v;
    __syncthreads();
    if (t == 0) {
        int acc = 0;
        #pragma unroll
        for (int i = 0; i < 8; i++) { woff[i] = acc; acc += wsum[i]; }
    }
    __syncthreads();

    int incl = v + woff[w];
    int excl = incl - s;
    reinterpret_cast<int2*>(g_voxlocal)[blockIdx.x * 256 + t] =
        make_int2(excl, excl + c.x);
    if (t == 255) g_bsum[blockIdx.x] = incl;
    reinterpret_cast<int2*>(g_cnt)[blockIdx.x * 256 + t] = make_int2(0, 0);
}

// ---------------------------------------------------------------------------
// Kernel 2b: exclusive scan of the 512 chunk totals (one block, 512 threads).
// ---------------------------------------------------------------------------
__global__ void scan_top_kernel() {
    __shared__ int wsum[16];
    __shared__ int woff[16];
    int t = threadIdx.x;
    int lane = t & 31, w = t >> 5;

    int s = g_bsum[t];
    int v = s;
    #pragma unroll
    for (int d = 1; d < 32; d <<= 1) {
        int u = __shfl_up_sync(0xffffffffu, v, d);
        if (lane >= d) v += u;
    }
    if (lane == 31) wsum[w] = v;
    __syncthreads();
    if (t == 0) {
        int acc = 0;
        #pragma unroll
        for (int i = 0; i < 16; i++) { woff[i] = acc; acc += wsum[i]; }
    }
    __syncthreads();

    int incl = v + woff[w];
    g_boff[t] = incl - s;
    if (t == 511) g_boff[512] = incl;    // == NPTS_TOT
}

// ---------------------------------------------------------------------------
// Kernel 3: permute-transpose for one 32-channel half. Tile [32 ch][64 pts]
// -> per-point 128B rows written at the point's sorted slot.
// ---------------------------------------------------------------------------
__global__ void permute_half_kernel(const float* __restrict__ feats, int h) {
    __shared__ float s[CH * 65];
    __shared__ int sslot[64];

    int t  = threadIdx.x;                 // 256 threads
    int b  = blockIdx.x >> 10;            // 8192 blocks = 8 x 1024
    int n0 = (blockIdx.x & 1023) * 64;

    // load 32 channels x 64 points (coalesced float4): 512 float4 / 256 thr
    #pragma unroll
    for (int i = 0; i < 2; i++) {
        int j4 = i * 256 + t;             // 0..511
        int c  = j4 >> 4;                 // 0..31
        int nq = (j4 & 15) * 4;
        float4 v = *reinterpret_cast<const float4*>(
            feats + (((size_t)(b * CC + h * CH + c)) << 16) + n0 + nq);
        float* sp = &s[c * 65 + nq];
        sp[0] = v.x; sp[1] = v.y; sp[2] = v.z; sp[3] = v.w;
    }
    if (t < 64) {
        int pt = (b << 16) + n0 + t;
        int gi = g_idx[pt];
        sslot[t] = g_voxlocal[gi] + g_boff[gi >> 9] + (int)g_rank[pt];
    }
    __syncthreads();

    // write: 4 threads per point, each 8 channels (2 x float4) -> 128B/point
    int p = t >> 2;
    int q = t & 3;
    size_t dst = (size_t)sslot[p] * CH + q * 8;
    #pragma unroll
    for (int k = 0; k < 2; k++) {
        int c0 = q * 8 + k * 4;
        float4 w;
        w.x = s[(c0 + 0) * 65 + p];
        w.y = s[(c0 + 1) * 65 + p];
        w.z = s[(c0 + 2) * 65 + p];
        w.w = s[(c0 + 3) * 65 + p];
        *reinterpret_cast<float4*>(&g_featT[dst + k * 4]) = w;
    }
}

// ---------------------------------------------------------------------------
// Kernel 4: gather + finalize for one 32-channel half. Block = 64 consecutive
// voxels (contiguous point rows). 4 threads/voxel x 8 channels, register
// accumulation, divide, smem transpose, coalesced [C][vox] write.
// ---------------------------------------------------------------------------
__global__ void gather_half_kernel(float* __restrict__ out, int h) {
    __shared__ float s[64 * 33];

    int t   = threadIdx.x;                // 256 threads
    int gv0 = blockIdx.x * 64;            // 4096 blocks
    int vl  = t >> 2;                     // local voxel 0..63
    int q   = t & 3;                      // channel quarter (8 ch)

    int i0 = gv0 + vl;
    int i1 = i0 + 1;
    int off0 = g_voxlocal[i0] + g_boff[i0 >> 9];
    int off1 = g_voxlocal[i1] + g_boff[i1 >> 9];

    float4 a0 = make_float4(0.f, 0.f, 0.f, 0.f);
    float4 a1 = a0;

    int p = off0;
    for (; p + 1 < off1; p += 2) {       // 2-point unroll for MLP
        const float4* r0 = reinterpret_cast<const float4*>(
            &g_featT[(size_t)p * CH + q * 8]);
        const float4* r1 = reinterpret_cast<const float4*>(
            &g_featT[(size_t)(p + 1) * CH + q * 8]);
        float4 u0 = r0[0], u1 = r0[1], w0 = r1[0], w1 = r1[1];
        a0.x += u0.x; a0.y += u0.y; a0.z += u0.z; a0.w += u0.w;
        a1.x += u1.x; a1.y += u1.y; a1.z += u1.z; a1.w += u1.w;
        a0.x += w0.x; a0.y += w0.y; a0.z += w0.z; a0.w += w0.w;
        a1.x += w1.x; a1.y += w1.y; a1.z += w1.z; a1.w += w1.w;
    }
    if (p < off1) {
        const float4* r0 = reinterpret_cast<const float4*>(
            &g_featT[(size_t)p * CH + q * 8]);
        float4 u0 = r0[0], u1 = r0[1];
        a0.x += u0.x; a0.y += u0.y; a0.z += u0.z; a0.w += u0.w;
        a1.x += u1.x; a1.y += u1.y; a1.z += u1.z; a1.w += u1.w;
    }

    float inv = 1.0f / fmaxf((float)(off1 - off0), 1.0f);
    float* sp = &s[vl * 33 + q * 8];
    sp[0] = a0.x * inv; sp[1] = a0.y * inv; sp[2] = a0.z * inv; sp[3] = a0.w * inv;
    sp[4] = a1.x * inv; sp[5] = a1.y * inv; sp[6] = a1.z * inv; sp[7] = a1.w * inv;
    __syncthreads();

    int b     = gv0 >> 15;                // / R3
    int vbase = gv0 & (R3 - 1);
    #pragma unroll
    for (int it = 0; it < 8; it++) {
        int c   = it * 4 + (t >> 6);      // 0..31
        int vl2 = t & 63;
        out[((size_t)(b * CC + h * CH + c)) * R3 + vbase + vl2] = s[vl2 * 33 + c];
    }
}

// ---------------------------------------------------------------------------
extern "C" void kernel_launch(void* const* d_in, const int* in_sizes, int n_in,
                              void* d_out, int out_size) {
    const float* feats  = (const float*)d_in[0];   // [B, C, N]
    const float* coords = (const float*)d_in[1];   // [B, 3, N]
    float* out = (float*)d_out;

    float* norm_out = (out_size >= VOX_ELEMS + NORM_ELEMS) ? (out + VOX_ELEMS)
                                                           : nullptr;

    point_kernel<<<NPTS_TOT / 4 / 256, 256>>>(coords, norm_out);
    scan_chunk_kernel<<<512, 256>>>();
    scan_top_kernel<<<1, 512>>>();
    permute_half_kernel<<<BB * (NPTS / 64), 256>>>(feats, 0);
    gather_half_kernel<<<NVOX / 64, 256>>>(out, 0);
    permute_half_kernel<<<BB * (NPTS / 64), 256>>>(feats, 1);
    gather_half_kernel<<<NVOX / 64, 256>>>(out, 1);
}

// round 13
// speedup vs baseline: 1.1611x; 1.1611x over previous
#include <cuda_runtime.h>
#include <cuda_bf16.h>
#include <cstdint>

// Problem constants (fixed by setup_inputs)
#define BB    8
#define CC    64
#define NPTS  65536
#define RR    32
#define R3    (RR*RR*RR)           // 32768
#define NVOX  (BB*R3)              // 262144
#define NPTS_TOT (BB*NPTS)         // 524288
#define VOX_ELEMS  (BB*CC*R3)      // 16777216
#define NORM_ELEMS (BB*3*NPTS)     // 1572864
#define CH    32                    // channels per pass (2 passes)

// Scratch (device globals, zero-init at load).
__device__ float g_featT[(size_t)NPTS_TOT * CH];  // 64 MB scratch, L2-pinned via evict_last policy
__device__ int   g_cnt[NVOX];                     // per-voxel counts (reset each launch)
__device__ int   g_voxlocal[NVOX + 1];            // chunk-local exclusive offsets
__device__ int   g_bsum[512];                     // chunk totals
__device__ int   g_boff[513];                     // chunk exclusive prefix
__device__ int   g_idx[NPTS_TOT];
__device__ int   g_slot[NPTS_TOT];                // sorted slot, computed pass 0, reused pass 1
__device__ unsigned short g_rank[NPTS_TOT];

// ---------------------------------------------------------------------------
// L2 eviction policies via createpolicy + cache_hint (legal for any width)
// ---------------------------------------------------------------------------
__device__ __forceinline__ uint64_t mkpol_evict_first() {
    uint64_t p;
    asm("createpolicy.fractional.L2::evict_first.b64 %0, 1.0;" : "=l"(p));
    return p;
}
__device__ __forceinline__ uint64_t mkpol_evict_last() {
    uint64_t p;
    asm("createpolicy.fractional.L2::evict_last.b64 %0, 1.0;" : "=l"(p));
    return p;
}
__device__ __forceinline__ float4 ldg_pol_nc(const float* p, uint64_t pol) {
    float4 v;
    asm volatile("ld.global.nc.L2::cache_hint.v4.f32 {%0,%1,%2,%3}, [%4], %5;"
                 : "=f"(v.x), "=f"(v.y), "=f"(v.z), "=f"(v.w) : "l"(p), "l"(pol));
    return v;
}
__device__ __forceinline__ float4 ldg_pol(const float* p, uint64_t pol) {
    float4 v;
    asm volatile("ld.global.L2::cache_hint.v4.f32 {%0,%1,%2,%3}, [%4], %5;"
                 : "=f"(v.x), "=f"(v.y), "=f"(v.z), "=f"(v.w) : "l"(p), "l"(pol));
    return v;
}
__device__ __forceinline__ void stg_pol(float* p, float4 v, uint64_t pol) {
    asm volatile("st.global.L2::cache_hint.v4.f32 [%0], {%1,%2,%3,%4}, %5;"
                 :: "l"(p), "f"(v.x), "f"(v.y), "f"(v.z), "f"(v.w), "l"(pol) : "memory");
}
__device__ __forceinline__ void stg_pol1(float* p, float v, uint64_t pol) {
    asm volatile("st.global.L2::cache_hint.f32 [%0], %1, %2;"
                 :: "l"(p), "f"(v), "l"(pol) : "memory");
}

// ---------------------------------------------------------------------------
// Kernel 1: per-point quantization, 4 points/thread.
// ---------------------------------------------------------------------------
__global__ void point_kernel(const float* __restrict__ coords,
                             float* __restrict__ norm_out) {
    uint64_t pf = mkpol_evict_first();
    int tid = blockIdx.x * blockDim.x + threadIdx.x;  // NPTS_TOT/4 threads
    int pt0 = tid * 4;
    int b = pt0 >> 16;
    int n = pt0 & (NPTS - 1);

    const float* cb = coords + (size_t)b * 3 * NPTS + n;
    float4 x4 = ldg_pol_nc(cb, pf);
    float4 y4 = ldg_pol_nc(cb + NPTS, pf);
    float4 z4 = ldg_pol_nc(cb + 2 * NPTS, pf);

    float nx[4] = {x4.x, x4.y, x4.z, x4.w};
    float ny[4] = {y4.x, y4.y, y4.z, y4.w};
    float nz[4] = {z4.x, z4.y, z4.z, z4.w};
    int gidx[4];
    #pragma unroll
    for (int i = 0; i < 4; i++) {
        nx[i] = fminf(fmaxf(nx[i] * (float)RR, 0.0f), (float)(RR - 1));
        ny[i] = fminf(fmaxf(ny[i] * (float)RR, 0.0f), (float)(RR - 1));
        nz[i] = fminf(fmaxf(nz[i] * (float)RR, 0.0f), (float)(RR - 1));
        int vx = __float2int_rn(nx[i]);   // round-half-even == jnp.round
        int vy = __float2int_rn(ny[i]);
        int vz = __float2int_rn(nz[i]);
        gidx[i] = b * R3 + (vx * RR + vy) * RR + vz;
    }

    if (norm_out) {
        float* nb = norm_out + (size_t)b * 3 * NPTS + n;
        stg_pol(nb,            make_float4(nx[0], nx[1], nx[2], nx[3]), pf);
        stg_pol(nb + NPTS,     make_float4(ny[0], ny[1], ny[2], ny[3]), pf);
        stg_pol(nb + 2 * NPTS, make_float4(nz[0], nz[1], nz[2], nz[3]), pf);
    }

    *reinterpret_cast<int4*>(&g_idx[pt0]) = make_int4(gidx[0], gidx[1], gidx[2], gidx[3]);

    unsigned short r[4];
    #pragma unroll
    for (int i = 0; i < 4; i++)
        r[i] = (unsigned short)atomicAdd(&g_cnt[gidx[i]], 1);
    *reinterpret_cast<ushort4*>(&g_rank[pt0]) = make_ushort4(r[0], r[1], r[2], r[3]);
}

// ---------------------------------------------------------------------------
// Kernel 2a: per-chunk (512 counts) local exclusive scan via warp shuffles.
// ---------------------------------------------------------------------------
__global__ void scan_chunk_kernel() {
    __shared__ int wsum[8];
    __shared__ int woff[8];
    int t = threadIdx.x;                 // 256 threads
    int lane = t & 31, w = t >> 5;

    int2 c = reinterpret_cast<const int2*>(g_cnt)[blockIdx.x * 256 + t];
    int s = c.x + c.y;

    int v = s;
    #pragma unroll
    for (int d = 1; d < 32; d <<= 1) {
        int u = __shfl_up_sync(0xffffffffu, v, d);
        if (lane >= d) v += u;
    }
    if (lane == 31) wsum[w] = v;
    __syncthreads();
    if (t == 0) {
        int acc = 0;
        #pragma unroll
        for (int i = 0; i < 8; i++) { woff[i] = acc; acc += wsum[i]; }
    }
    __syncthreads();

    int incl = v + woff[w];
    int excl = incl - s;
    reinterpret_cast<int2*>(g_voxlocal)[blockIdx.x * 256 + t] =
        make_int2(excl, excl + c.x);
    if (t == 255) g_bsum[blockIdx.x] = incl;
    reinterpret_cast<int2*>(g_cnt)[blockIdx.x * 256 + t] = make_int2(0, 0);
}

// ---------------------------------------------------------------------------
// Kernel 2b: exclusive scan of the 512 chunk totals.
// ---------------------------------------------------------------------------
__global__ void scan_top_kernel() {
    __shared__ int wsum[16];
    __shared__ int woff[16];
    int t = threadIdx.x;
    int lane = t & 31, w = t >> 5;

    int s = g_bsum[t];
    int v = s;
    #pragma unroll
    for (int d = 1; d < 32; d <<= 1) {
        int u = __shfl_up_sync(0xffffffffu, v, d);
        if (lane >= d) v += u;
    }
    if (lane == 31) wsum[w] = v;
    __syncthreads();
    if (t == 0) {
        int acc = 0;
        #pragma unroll
        for (int i = 0; i < 16; i++) { woff[i] = acc; acc += wsum[i]; }
    }
    __syncthreads();

    int incl = v + woff[w];
    g_boff[t] = incl - s;
    if (t == 511) g_boff[512] = incl;    // == NPTS_TOT
}

// ---------------------------------------------------------------------------
// Kernel 3: permute-transpose for one 32-channel half.
// feats: streaming reads (evict_first); featT: L2-pinned writes (evict_last).
// Pass 0 computes + caches sorted slots; pass 1 reloads them.
// ---------------------------------------------------------------------------
__global__ void permute_half_kernel(const float* __restrict__ feats, int h) {
    __shared__ float s[CH * 65];
    __shared__ int sslot[64];

    uint64_t pf = mkpol_evict_first();
    uint64_t pl = mkpol_evict_last();

    int t  = threadIdx.x;                 // 256 threads
    int b  = blockIdx.x >> 10;            // 8192 blocks = 8 x 1024
    int n0 = (blockIdx.x & 1023) * 64;

    // load 32 channels x 64 points (coalesced float4)
    #pragma unroll
    for (int i = 0; i < 2; i++) {
        int j4 = i * 256 + t;             // 0..511
        int c  = j4 >> 4;                 // 0..31
        int nq = (j4 & 15) * 4;
        float4 v = ldg_pol_nc(feats + (((size_t)(b * CC + h * CH + c)) << 16) + n0 + nq, pf);
        float* sp = &s[c * 65 + nq];
        sp[0] = v.x; sp[1] = v.y; sp[2] = v.z; sp[3] = v.w;
    }
    if (t < 64) {
        int pt = (b << 16) + n0 + t;
        int slot;
        if (h == 0) {
            int gi = g_idx[pt];
            slot = g_voxlocal[gi] + g_boff[gi >> 9] + (int)g_rank[pt];
            g_slot[pt] = slot;
        } else {
            slot = g_slot[pt];
        }
        sslot[t] = slot;
    }
    __syncthreads();

    // write: 4 threads per point, each 8 channels (2 x float4) -> 128B/point
    int p = t >> 2;
    int q = t & 3;
    size_t dst = (size_t)sslot[p] * CH + q * 8;
    #pragma unroll
    for (int k = 0; k < 2; k++) {
        int c0 = q * 8 + k * 4;
        float4 w;
        w.x = s[(c0 + 0) * 65 + p];
        w.y = s[(c0 + 1) * 65 + p];
        w.z = s[(c0 + 2) * 65 + p];
        w.w = s[(c0 + 3) * 65 + p];
        stg_pol(&g_featT[dst + k * 4], w, pl);
    }
}

// ---------------------------------------------------------------------------
// Kernel 4: gather + finalize for one 32-channel half.
// featT reads stay L2-pinned (evict_last); out writes stream (evict_first).
// ---------------------------------------------------------------------------
__global__ void gather_half_kernel(float* __restrict__ out, int h) {
    __shared__ float s[64 * 33];

    uint64_t pf = mkpol_evict_first();
    uint64_t pl = mkpol_evict_last();

    int t   = threadIdx.x;                // 256 threads
    int gv0 = blockIdx.x * 64;            // 4096 blocks
    int vl  = t >> 2;                     // local voxel 0..63
    int q   = t & 3;                      // channel quarter (8 ch)

    int i0 = gv0 + vl;
    int i1 = i0 + 1;
    int off0 = g_voxlocal[i0] + g_boff[i0 >> 9];
    int off1 = g_voxlocal[i1] + g_boff[i1 >> 9];

    float4 a0 = make_float4(0.f, 0.f, 0.f, 0.f);
    float4 a1 = a0;

    int p = off0;
    for (; p + 1 < off1; p += 2) {       // 2-point unroll for MLP
        const float* r0 = &g_featT[(size_t)p * CH + q * 8];
        const float* r1 = &g_featT[(size_t)(p + 1) * CH + q * 8];
        float4 u0 = ldg_pol(r0, pl),     u1 = ldg_pol(r0 + 4, pl);
        float4 w0 = ldg_pol(r1, pl),     w1 = ldg_pol(r1 + 4, pl);
        a0.x += u0.x; a0.y += u0.y; a0.z += u0.z; a0.w += u0.w;
        a1.x += u1.x; a1.y += u1.y; a1.z += u1.z; a1.w += u1.w;
        a0.x += w0.x; a0.y += w0.y; a0.z += w0.z; a0.w += w0.w;
        a1.x += w1.x; a1.y += w1.y; a1.z += w1.z; a1.w += w1.w;
    }
    if (p < off1) {
        const float* r0 = &g_featT[(size_t)p * CH + q * 8];
        float4 u0 = ldg_pol(r0, pl), u1 = ldg_pol(r0 + 4, pl);
        a0.x += u0.x; a0.y += u0.y; a0.z += u0.z; a0.w += u0.w;
        a1.x += u1.x; a1.y += u1.y; a1.z += u1.z; a1.w += u1.w;
    }

    float inv = 1.0f / fmaxf((float)(off1 - off0), 1.0f);
    float* sp = &s[vl * 33 + q * 8];
    sp[0] = a0.x * inv; sp[1] = a0.y * inv; sp[2] = a0.z * inv; sp[3] = a0.w * inv;
    sp[4] = a1.x * inv; sp[5] = a1.y * inv; sp[6] = a1.z * inv; sp[7] = a1.w * inv;
    __syncthreads();

    int b     = gv0 >> 15;                // / R3
    int vbase = gv0 & (R3 - 1);
    #pragma unroll
    for (int it = 0; it < 8; it++) {
        int c   = it * 4 + (t >> 6);      // 0..31
        int vl2 = t & 63;
        stg_pol1(out + ((size_t)(b * CC + h * CH + c)) * R3 + vbase + vl2,
                 s[vl2 * 33 + c], pf);
    }
}

// ---------------------------------------------------------------------------
extern "C" void kernel_launch(void* const* d_in, const int* in_sizes, int n_in,
                              void* d_out, int out_size) {
    const float* feats  = (const float*)d_in[0];   // [B, C, N]
    const float* coords = (const float*)d_in[1];   // [B, 3, N]
    float* out = (float*)d_out;

    float* norm_out = (out_size >= VOX_ELEMS + NORM_ELEMS) ? (out + VOX_ELEMS)
                                                           : nullptr;

    point_kernel<<<NPTS_TOT / 4 / 256, 256>>>(coords, norm_out);
    scan_chunk_kernel<<<512, 256>>>();
    scan_top_kernel<<<1, 512>>>();
    permute_half_kernel<<<BB * (NPTS / 64), 256>>>(feats, 0);
    gather_half_kernel<<<NVOX / 64, 256>>>(out, 0);
    permute_half_kernel<<<BB * (NPTS / 64), 256>>>(feats, 1);
    gather_half_kernel<<<NVOX / 64, 256>>>(out, 1);
}